// round 2
// baseline (speedup 1.0000x reference)
#include <cuda_runtime.h>
#include <math.h>

#define N_ELEC 64
#define N_NUC  16
#define N_PART 80
#define BASIS  32
#define KDIM   128
#define DDIM   128
#define BSZ    256
#define LAYERS 3

// Scratch (no cudaMalloc allowed)
__device__ float g_zs[BSZ * N_PART * KDIM];      // (b, j, k) post embed_in / nuc
__device__ float g_zsout[BSZ * N_ELEC * KDIM];   // cfconv output

__device__ __forceinline__ float ssp_f(float x) {
    // softplus(x) - ln2, numerically stable; |x| is small here so fast-math intrinsics are fine
    float ax = fabsf(x);
    return fmaxf(x, 0.0f) + __logf(1.0f + __expf(-ax)) - 0.69314718055994530942f;
}

// ---------------------------------------------------------------------------
// Init: xs (= d_out) <- broadcast electron embedding; zs nuc rows <- embedding_nuc
// ---------------------------------------------------------------------------
__global__ void init_kernel(const float* __restrict__ emb_e,
                            const float* __restrict__ emb_n,
                            float* __restrict__ xs) {
    int idx = blockIdx.x * blockDim.x + threadIdx.x;
    const int total_x = BSZ * N_ELEC * DDIM;
    const int total_n = BSZ * N_NUC * KDIM;
    if (idx < total_x) {
        xs[idx] = emb_e[idx % (N_ELEC * DDIM)];
    }
    if (idx < total_n) {
        int b = idx / (N_NUC * KDIM);
        int r = idx % (N_NUC * KDIM);
        g_zs[b * (N_PART * KDIM) + N_ELEC * KDIM + r] = emb_n[r];
    }
}

// ---------------------------------------------------------------------------
// zs (electron rows) = xs @ eiW   — one block per (b, j), 128 threads
// ---------------------------------------------------------------------------
__global__ void zs_elec_kernel(const float* __restrict__ xs,
                               const float* __restrict__ eiW) {
    int bj = blockIdx.x;                  // b*64 + j
    int b  = bj >> 6;
    int j  = bj & 63;
    __shared__ float xrow[DDIM];
    int k = threadIdx.x;
    xrow[k] = xs[(size_t)bj * DDIM + k];
    __syncthreads();
    float acc = 0.0f;
#pragma unroll 8
    for (int d = 0; d < DDIM; ++d)
        acc = fmaf(xrow[d], eiW[d * KDIM + k], acc);
    g_zs[(b * N_PART + j) * KDIM + k] = acc;
}

// ---------------------------------------------------------------------------
// Main fused kernel: one block per (b, i), 256 threads.
//   h = ssp(dists[b,i] @ kW1 + kb1)            (80 x 128, in SMEM)
//   W = h @ kW2 + kb2                          (80 x 128, in registers)
//   zs_out[b,i,k] = sum_{j != i} W[j,k] * zs[b,j,k]
// ---------------------------------------------------------------------------
__global__ void __launch_bounds__(256, 2) cfconv_kernel(
    const float* __restrict__ dists,
    const float* __restrict__ kW1, const float* __restrict__ kb1,
    const float* __restrict__ kW2, const float* __restrict__ kb2)
{
    __shared__ float sh[N_PART * KDIM];   // 40 KB: h matrix, later reused for reduction

    const int bi  = blockIdx.x;           // b*64 + i
    const int b   = bi >> 6;
    const int i   = bi & 63;
    const int tid = threadIdx.x;

    // ---- Phase 1: h[j,m] = ssp(sum_f dists[j,f] * kW1[f,m] + kb1[m]) ----
    {
        const int m    = tid & 127;
        const int half = tid >> 7;
        const float* dptr = dists + (size_t)bi * (N_PART * BASIS);

        float w1[BASIS];
#pragma unroll
        for (int f = 0; f < BASIS; ++f)
            w1[f] = kW1[f * KDIM + m];    // coalesced per f across the warp
        const float b1 = kb1[m];

        const int j0 = half * 40;
        for (int j = j0; j < j0 + 40; ++j) {
            const float4* row = reinterpret_cast<const float4*>(dptr + j * BASIS);
            float acc = b1;
#pragma unroll
            for (int f4 = 0; f4 < 8; ++f4) {
                float4 dv = row[f4];      // warp-uniform address: 1 sector, L1
                acc = fmaf(dv.x, w1[4 * f4 + 0], acc);
                acc = fmaf(dv.y, w1[4 * f4 + 1], acc);
                acc = fmaf(dv.z, w1[4 * f4 + 2], acc);
                acc = fmaf(dv.w, w1[4 * f4 + 3], acc);
            }
            sh[j * KDIM + m] = ssp_f(acc);
        }
    }
    __syncthreads();

    // ---- Phase 2: register-tiled GEMM h @ kW2, fused mask + zs reduction ----
    const int tj = tid >> 4;              // 0..15  -> j = tj + 16*s, s=0..4
    const int tk = tid & 15;              // 0..15  -> k = 8*tk .. 8*tk+7
    const int k0 = tk * 8;

    float acc[40];
#pragma unroll
    for (int x = 0; x < 40; ++x) acc[x] = 0.0f;

#pragma unroll 2
    for (int m = 0; m < KDIM; ++m) {
        const float4 wa = *reinterpret_cast<const float4*>(kW2 + m * KDIM + k0);
        const float4 wb = *reinterpret_cast<const float4*>(kW2 + m * KDIM + k0 + 4);
#pragma unroll
        for (int s = 0; s < 5; ++s) {
            const float hv = sh[(tj + s * 16) * KDIM + m];   // 2 distinct addrs/warp: broadcast
            float* a = acc + s * 8;
            a[0] = fmaf(hv, wa.x, a[0]);
            a[1] = fmaf(hv, wa.y, a[1]);
            a[2] = fmaf(hv, wa.z, a[2]);
            a[3] = fmaf(hv, wa.w, a[3]);
            a[4] = fmaf(hv, wb.x, a[4]);
            a[5] = fmaf(hv, wb.y, a[5]);
            a[6] = fmaf(hv, wb.z, a[6]);
            a[7] = fmaf(hv, wb.w, a[7]);
        }
    }

    // epilogue: add kb2, mask j==i, weight by zs, partial-sum over this thread's 5 j's
    const float4 cba = *reinterpret_cast<const float4*>(kb2 + k0);
    const float4 cbb = *reinterpret_cast<const float4*>(kb2 + k0 + 4);
    const float* zsb = g_zs + (size_t)b * (N_PART * KDIM);

    float o[8];
#pragma unroll
    for (int q = 0; q < 8; ++q) o[q] = 0.0f;

#pragma unroll
    for (int s = 0; s < 5; ++s) {
        const int j = tj + s * 16;
        if (j != i) {
            const float4 za = *reinterpret_cast<const float4*>(zsb + j * KDIM + k0);
            const float4 zb = *reinterpret_cast<const float4*>(zsb + j * KDIM + k0 + 4);
            const float* a = acc + s * 8;
            o[0] = fmaf(a[0] + cba.x, za.x, o[0]);
            o[1] = fmaf(a[1] + cba.y, za.y, o[1]);
            o[2] = fmaf(a[2] + cba.z, za.z, o[2]);
            o[3] = fmaf(a[3] + cba.w, za.w, o[3]);
            o[4] = fmaf(a[4] + cbb.x, zb.x, o[4]);
            o[5] = fmaf(a[5] + cbb.y, zb.y, o[5]);
            o[6] = fmaf(a[6] + cbb.z, zb.z, o[6]);
            o[7] = fmaf(a[7] + cbb.w, zb.w, o[7]);
        }
    }

    // ---- cross-thread reduction over tj (16 partials per k), reuse sh ----
    __syncthreads();                      // all sh reads done before aliasing
    float* sred = sh;                     // 16 x 128 floats
    float4* dst = reinterpret_cast<float4*>(sred + tj * KDIM + k0);
    dst[0] = make_float4(o[0], o[1], o[2], o[3]);
    dst[1] = make_float4(o[4], o[5], o[6], o[7]);
    __syncthreads();

    if (tid < KDIM) {
        float ssum = 0.0f;
#pragma unroll
        for (int r = 0; r < 16; ++r) ssum += sred[r * KDIM + tid];
        g_zsout[(size_t)bi * KDIM + tid] = ssum;
    }
}

// ---------------------------------------------------------------------------
// Output MLP: xs += ssp(zs_out @ eoW1 + eob1) @ eoW2 + eob2
// one block per (b, i), 128 threads
// ---------------------------------------------------------------------------
__global__ void out_mlp_kernel(const float* __restrict__ eoW1,
                               const float* __restrict__ eob1,
                               const float* __restrict__ eoW2,
                               const float* __restrict__ eob2,
                               float* __restrict__ xs) {
    int bi = blockIdx.x;
    __shared__ float zrow[KDIM];
    __shared__ float trow[KDIM];
    int k = threadIdx.x;
    zrow[k] = g_zsout[(size_t)bi * KDIM + k];
    __syncthreads();
    float acc = eob1[k];
#pragma unroll 8
    for (int d = 0; d < KDIM; ++d)
        acc = fmaf(zrow[d], eoW1[d * DDIM + k], acc);
    trow[k] = ssp_f(acc);
    __syncthreads();
    float acc2 = eob2[k];
#pragma unroll 8
    for (int d = 0; d < DDIM; ++d)
        acc2 = fmaf(trow[d], eoW2[d * DDIM + k], acc2);
    xs[(size_t)bi * DDIM + k] += acc2;
}

// ---------------------------------------------------------------------------
extern "C" void kernel_launch(void* const* d_in, const int* in_sizes, int n_in,
                              void* d_out, int out_size) {
    const float* dists = (const float*)d_in[0];   // (256,64,80,32)
    const float* emb_e = (const float*)d_in[1];   // (64,128)
    const float* emb_n = (const float*)d_in[2];   // (16,128)
    const float* kW1   = (const float*)d_in[3];   // (3,32,128)
    const float* kb1   = (const float*)d_in[4];   // (3,128)
    const float* kW2   = (const float*)d_in[5];   // (3,128,128)
    const float* kb2   = (const float*)d_in[6];   // (3,128)
    const float* eiW   = (const float*)d_in[7];   // (3,128,128)
    const float* eoW1  = (const float*)d_in[8];   // (3,128,128)
    const float* eob1  = (const float*)d_in[9];   // (3,128)
    const float* eoW2  = (const float*)d_in[10];  // (3,128,128)
    const float* eob2  = (const float*)d_in[11];  // (3,128)
    float* xs = (float*)d_out;                    // (256,64,128), doubles as state

    const int nbi = BSZ * N_ELEC;  // 16384

    init_kernel<<<(BSZ * N_ELEC * DDIM + 255) / 256, 256>>>(emb_e, emb_n, xs);

    for (int l = 0; l < LAYERS; ++l) {
        zs_elec_kernel<<<nbi, 128>>>(xs, eiW + (size_t)l * DDIM * KDIM);
        cfconv_kernel<<<nbi, 256>>>(dists,
                                    kW1 + (size_t)l * BASIS * KDIM,
                                    kb1 + (size_t)l * KDIM,
                                    kW2 + (size_t)l * KDIM * KDIM,
                                    kb2 + (size_t)l * KDIM);
        out_mlp_kernel<<<nbi, 128>>>(eoW1 + (size_t)l * KDIM * DDIM,
                                     eob1 + (size_t)l * DDIM,
                                     eoW2 + (size_t)l * DDIM * DDIM,
                                     eob2 + (size_t)l * DDIM,
                                     xs);
    }
}

// round 3
// speedup vs baseline: 1.0052x; 1.0052x over previous
#include <cuda_runtime.h>
#include <math.h>

#define N_ELEC 64
#define N_NUC  16
#define N_PART 80
#define BASIS  32
#define KDIM   128
#define DDIM   128
#define BSZ    256
#define LAYERS 3

// Scratch (no cudaMalloc allowed)
__device__ float g_zs[BSZ * N_PART * KDIM];      // (b, j, k) post embed_in / nuc
__device__ float g_zsout[BSZ * N_ELEC * KDIM];   // cfconv output

__device__ __forceinline__ float ssp_f(float x) {
    // softplus(x) - ln2, numerically stable; |x| is small here so fast-math intrinsics are fine
    float ax = fabsf(x);
    return fmaxf(x, 0.0f) + __logf(1.0f + __expf(-ax)) - 0.69314718055994530942f;
}

// ---------------------------------------------------------------------------
// Init: xs (= d_out) <- broadcast electron embedding; zs nuc rows <- embedding_nuc
// ---------------------------------------------------------------------------
__global__ void init_kernel(const float* __restrict__ emb_e,
                            const float* __restrict__ emb_n,
                            float* __restrict__ xs) {
    int idx = blockIdx.x * blockDim.x + threadIdx.x;
    const int total_x = BSZ * N_ELEC * DDIM;
    const int total_n = BSZ * N_NUC * KDIM;
    if (idx < total_x) {
        xs[idx] = emb_e[idx % (N_ELEC * DDIM)];
    }
    if (idx < total_n) {
        int b = idx / (N_NUC * KDIM);
        int r = idx % (N_NUC * KDIM);
        g_zs[b * (N_PART * KDIM) + N_ELEC * KDIM + r] = emb_n[r];
    }
}

// ---------------------------------------------------------------------------
// zs (electron rows) = xs @ eiW   — one block per (b, j), 128 threads
// ---------------------------------------------------------------------------
__global__ void zs_elec_kernel(const float* __restrict__ xs,
                               const float* __restrict__ eiW) {
    int bj = blockIdx.x;                  // b*64 + j
    int b  = bj >> 6;
    int j  = bj & 63;
    __shared__ float xrow[DDIM];
    int k = threadIdx.x;
    xrow[k] = xs[(size_t)bj * DDIM + k];
    __syncthreads();
    float acc = 0.0f;
#pragma unroll 8
    for (int d = 0; d < DDIM; ++d)
        acc = fmaf(xrow[d], eiW[d * KDIM + k], acc);
    g_zs[(b * N_PART + j) * KDIM + k] = acc;
}

// ---------------------------------------------------------------------------
// Main fused kernel: one block per (b, i), 256 threads.
//   h = ssp(dists[b,i] @ kW1 + kb1)            (80 x 128, in SMEM)
//   W = h @ kW2 + kb2                          (80 x 128, in registers)
//   zs_out[b,i,k] = sum_{j != i} W[j,k] * zs[b,j,k]
// ---------------------------------------------------------------------------
__global__ void __launch_bounds__(256, 2) cfconv_kernel(
    const float* __restrict__ dists,
    const float* __restrict__ kW1, const float* __restrict__ kb1,
    const float* __restrict__ kW2, const float* __restrict__ kb2)
{
    __shared__ float sh[N_PART * KDIM];   // 40 KB: h matrix, later reused for reduction

    const int bi  = blockIdx.x;           // b*64 + i
    const int b   = bi >> 6;
    const int i   = bi & 63;
    const int tid = threadIdx.x;

    // ---- Phase 1: h[j,m] = ssp(sum_f dists[j,f] * kW1[f,m] + kb1[m]) ----
    {
        const int m    = tid & 127;
        const int half = tid >> 7;
        const float* dptr = dists + (size_t)bi * (N_PART * BASIS);

        float w1[BASIS];
#pragma unroll
        for (int f = 0; f < BASIS; ++f)
            w1[f] = kW1[f * KDIM + m];    // coalesced per f across the warp
        const float b1 = kb1[m];

        const int j0 = half * 40;
        for (int j = j0; j < j0 + 40; ++j) {
            const float4* row = reinterpret_cast<const float4*>(dptr + j * BASIS);
            float acc = b1;
#pragma unroll
            for (int f4 = 0; f4 < 8; ++f4) {
                float4 dv = row[f4];      // warp-uniform address: 1 sector, L1
                acc = fmaf(dv.x, w1[4 * f4 + 0], acc);
                acc = fmaf(dv.y, w1[4 * f4 + 1], acc);
                acc = fmaf(dv.z, w1[4 * f4 + 2], acc);
                acc = fmaf(dv.w, w1[4 * f4 + 3], acc);
            }
            sh[j * KDIM + m] = ssp_f(acc);
        }
    }
    __syncthreads();

    // ---- Phase 2: register-tiled GEMM h @ kW2, fused mask + zs reduction ----
    const int tj = tid >> 4;              // 0..15  -> j = tj + 16*s, s=0..4
    const int tk = tid & 15;              // 0..15  -> k = 8*tk .. 8*tk+7
    const int k0 = tk * 8;

    float acc[40];
#pragma unroll
    for (int x = 0; x < 40; ++x) acc[x] = 0.0f;

#pragma unroll 2
    for (int m = 0; m < KDIM; ++m) {
        const float4 wa = *reinterpret_cast<const float4*>(kW2 + m * KDIM + k0);
        const float4 wb = *reinterpret_cast<const float4*>(kW2 + m * KDIM + k0 + 4);
#pragma unroll
        for (int s = 0; s < 5; ++s) {
            const float hv = sh[(tj + s * 16) * KDIM + m];   // 2 distinct addrs/warp: broadcast
            float* a = acc + s * 8;
            a[0] = fmaf(hv, wa.x, a[0]);
            a[1] = fmaf(hv, wa.y, a[1]);
            a[2] = fmaf(hv, wa.z, a[2]);
            a[3] = fmaf(hv, wa.w, a[3]);
            a[4] = fmaf(hv, wb.x, a[4]);
            a[5] = fmaf(hv, wb.y, a[5]);
            a[6] = fmaf(hv, wb.z, a[6]);
            a[7] = fmaf(hv, wb.w, a[7]);
        }
    }

    // epilogue: add kb2, mask j==i, weight by zs, partial-sum over this thread's 5 j's
    const float4 cba = *reinterpret_cast<const float4*>(kb2 + k0);
    const float4 cbb = *reinterpret_cast<const float4*>(kb2 + k0 + 4);
    const float* zsb = g_zs + (size_t)b * (N_PART * KDIM);

    float o[8];
#pragma unroll
    for (int q = 0; q < 8; ++q) o[q] = 0.0f;

#pragma unroll
    for (int s = 0; s < 5; ++s) {
        const int j = tj + s * 16;
        if (j != i) {
            const float4 za = *reinterpret_cast<const float4*>(zsb + j * KDIM + k0);
            const float4 zb = *reinterpret_cast<const float4*>(zsb + j * KDIM + k0 + 4);
            const float* a = acc + s * 8;
            o[0] = fmaf(a[0] + cba.x, za.x, o[0]);
            o[1] = fmaf(a[1] + cba.y, za.y, o[1]);
            o[2] = fmaf(a[2] + cba.z, za.z, o[2]);
            o[3] = fmaf(a[3] + cba.w, za.w, o[3]);
            o[4] = fmaf(a[4] + cbb.x, zb.x, o[4]);
            o[5] = fmaf(a[5] + cbb.y, zb.y, o[5]);
            o[6] = fmaf(a[6] + cbb.z, zb.z, o[6]);
            o[7] = fmaf(a[7] + cbb.w, zb.w, o[7]);
        }
    }

    // ---- cross-thread reduction over tj (16 partials per k), reuse sh ----
    __syncthreads();                      // all sh reads done before aliasing
    float* sred = sh;                     // 16 x 128 floats
    float4* dst = reinterpret_cast<float4*>(sred + tj * KDIM + k0);
    dst[0] = make_float4(o[0], o[1], o[2], o[3]);
    dst[1] = make_float4(o[4], o[5], o[6], o[7]);
    __syncthreads();

    if (tid < KDIM) {
        float ssum = 0.0f;
#pragma unroll
        for (int r = 0; r < 16; ++r) ssum += sred[r * KDIM + tid];
        g_zsout[(size_t)bi * KDIM + tid] = ssum;
    }
}

// ---------------------------------------------------------------------------
// Output MLP: xs += ssp(zs_out @ eoW1 + eob1) @ eoW2 + eob2
// one block per (b, i), 128 threads
// ---------------------------------------------------------------------------
__global__ void out_mlp_kernel(const float* __restrict__ eoW1,
                               const float* __restrict__ eob1,
                               const float* __restrict__ eoW2,
                               const float* __restrict__ eob2,
                               float* __restrict__ xs) {
    int bi = blockIdx.x;
    __shared__ float zrow[KDIM];
    __shared__ float trow[KDIM];
    int k = threadIdx.x;
    zrow[k] = g_zsout[(size_t)bi * KDIM + k];
    __syncthreads();
    float acc = eob1[k];
#pragma unroll 8
    for (int d = 0; d < KDIM; ++d)
        acc = fmaf(zrow[d], eoW1[d * DDIM + k], acc);
    trow[k] = ssp_f(acc);
    __syncthreads();
    float acc2 = eob2[k];
#pragma unroll 8
    for (int d = 0; d < DDIM; ++d)
        acc2 = fmaf(trow[d], eoW2[d * DDIM + k], acc2);
    xs[(size_t)bi * DDIM + k] += acc2;
}

// ---------------------------------------------------------------------------
extern "C" void kernel_launch(void* const* d_in, const int* in_sizes, int n_in,
                              void* d_out, int out_size) {
    const float* dists = (const float*)d_in[0];   // (256,64,80,32)
    const float* emb_e = (const float*)d_in[1];   // (64,128)
    const float* emb_n = (const float*)d_in[2];   // (16,128)
    const float* kW1   = (const float*)d_in[3];   // (3,32,128)
    const float* kb1   = (const float*)d_in[4];   // (3,128)
    const float* kW2   = (const float*)d_in[5];   // (3,128,128)
    const float* kb2   = (const float*)d_in[6];   // (3,128)
    const float* eiW   = (const float*)d_in[7];   // (3,128,128)
    const float* eoW1  = (const float*)d_in[8];   // (3,128,128)
    const float* eob1  = (const float*)d_in[9];   // (3,128)
    const float* eoW2  = (const float*)d_in[10];  // (3,128,128)
    const float* eob2  = (const float*)d_in[11];  // (3,128)
    float* xs = (float*)d_out;                    // (256,64,128), doubles as state

    const int nbi = BSZ * N_ELEC;  // 16384

    init_kernel<<<(BSZ * N_ELEC * DDIM + 255) / 256, 256>>>(emb_e, emb_n, xs);

    for (int l = 0; l < LAYERS; ++l) {
        zs_elec_kernel<<<nbi, 128>>>(xs, eiW + (size_t)l * DDIM * KDIM);
        cfconv_kernel<<<nbi, 256>>>(dists,
                                    kW1 + (size_t)l * BASIS * KDIM,
                                    kb1 + (size_t)l * KDIM,
                                    kW2 + (size_t)l * KDIM * KDIM,
                                    kb2 + (size_t)l * KDIM);
        out_mlp_kernel<<<nbi, 128>>>(eoW1 + (size_t)l * KDIM * DDIM,
                                     eob1 + (size_t)l * DDIM,
                                     eoW2 + (size_t)l * DDIM * DDIM,
                                     eob2 + (size_t)l * DDIM,
                                     xs);
    }
}

// round 5
// speedup vs baseline: 3.5772x; 3.5588x over previous
#include <cuda_runtime.h>
#include <math.h>
#include <stdint.h>

#define N_ELEC 64
#define N_NUC  16
#define N_PART 80
#define BASIS  32
#define KDIM   128
#define DDIM   128
#define BSZ    256
#define LAYERS 3
#define NBI    (BSZ * N_ELEC)

#define TILES_PER_CTA 16
#define CFC_GRID (NBI / TILES_PER_CTA)

#define DPAD 36     // dists smem row pad (floats)
#define HPAD 88     // h smem row pad (floats)
#define ZPAD 132    // zs smem row pad (floats)

// Scratch (no cudaMalloc allowed)
__device__ float g_zs[BSZ * N_PART * KDIM];      // (b, j, k)
__device__ float g_zsout[BSZ * N_ELEC * KDIM];   // cfconv output

__device__ __forceinline__ float ssp_f(float x) {
    float ax = fabsf(x);
    return fmaxf(x, 0.0f) + __logf(1.0f + __expf(-ax)) - 0.69314718055994530942f;
}

__device__ __forceinline__ uint32_t to_tf32(float x) {
    uint32_t u;
    asm("cvt.rna.tf32.f32 %0, %1;" : "=r"(u) : "f"(x));
    return u;
}

// m16n8k8 tf32 mma (baseline PTX, sm_80+; runs on tensor pipe via HMMA)
__device__ __forceinline__ void mma_tf32(float* d, const uint32_t* a,
                                         uint32_t b0, uint32_t b1) {
    asm volatile(
        "mma.sync.aligned.m16n8k8.row.col.f32.tf32.tf32.f32 "
        "{%0,%1,%2,%3}, {%4,%5,%6,%7}, {%8,%9}, {%0,%1,%2,%3};"
        : "+f"(d[0]), "+f"(d[1]), "+f"(d[2]), "+f"(d[3])
        : "r"(a[0]), "r"(a[1]), "r"(a[2]), "r"(a[3]), "r"(b0), "r"(b1));
}

// ---------------------------------------------------------------------------
__global__ void init_kernel(const float* __restrict__ emb_e,
                            const float* __restrict__ emb_n,
                            float* __restrict__ xs) {
    int idx = blockIdx.x * blockDim.x + threadIdx.x;
    const int total_x = BSZ * N_ELEC * DDIM;
    const int total_n = BSZ * N_NUC * KDIM;
    if (idx < total_x) xs[idx] = emb_e[idx % (N_ELEC * DDIM)];
    if (idx < total_n) {
        int b = idx / (N_NUC * KDIM);
        int r = idx % (N_NUC * KDIM);
        g_zs[b * (N_PART * KDIM) + N_ELEC * KDIM + r] = emb_n[r];
    }
}

// ---------------------------------------------------------------------------
// zs electron rows: 8 rows per block, weight reuse across rows
// ---------------------------------------------------------------------------
__global__ void __launch_bounds__(128) zs_elec_kernel(const float* __restrict__ xs,
                                                      const float* __restrict__ eiW) {
    int bj0 = blockIdx.x * 8;
    int b   = bj0 >> 6;
    int jb  = bj0 & 63;
    __shared__ float xr[8][DDIM];
    int k = threadIdx.x;
#pragma unroll
    for (int r = 0; r < 8; ++r) xr[r][k] = xs[(size_t)(bj0 + r) * DDIM + k];
    __syncthreads();
    float acc[8];
#pragma unroll
    for (int r = 0; r < 8; ++r) acc[r] = 0.0f;
#pragma unroll 4
    for (int d = 0; d < DDIM; ++d) {
        float w = eiW[d * KDIM + k];
#pragma unroll
        for (int r = 0; r < 8; ++r) acc[r] = fmaf(xr[r][d], w, acc[r]);
    }
#pragma unroll
    for (int r = 0; r < 8; ++r)
        g_zs[((size_t)b * N_PART + jb + r) * KDIM + k] = acc[r];
}

// ---------------------------------------------------------------------------
// cfconv via mma.sync tf32, persistent CTAs (16 tiles each, same batch b)
//   GEMM1: D1[m, j] = kW1^T(128x32) @ dists^T(32x80)   -> h = ssp(D1 + kb1)
//   GEMM2: D2[k, j] = kW2^T(128x128) @ h(128x80)
//   out[k] = sum_{j != i} (D2[k,j] + kb2[k]) * zs[b,j,k]
// Warp w owns 16 rows (m / k = w*16 .. w*16+15); j lives inside the warp.
// ---------------------------------------------------------------------------
extern __shared__ float cf_smem[];

__global__ void __launch_bounds__(256) cfconv_mma_kernel(
    const float* __restrict__ dists,
    const float* __restrict__ kW1, const float* __restrict__ kb1,
    const float* __restrict__ kW2, const float* __restrict__ kb2)
{
    float* d_s  = cf_smem;                                  // 80 x DPAD
    float* h_s  = cf_smem + N_PART * DPAD;                  // 128 x HPAD (tf32 bits)
    float* zs_s = cf_smem + N_PART * DPAD + KDIM * HPAD;    // 80 x ZPAD

    const int tid  = threadIdx.x;
    const int wid  = tid >> 5;
    const int lane = tid & 31;
    const int g    = lane >> 2;    // groupID 0..7
    const int tg   = lane & 3;     // thread-in-group 0..3
    const int m0   = wid * 16 + g; // this thread's rows (m for GEMM1, k for GEMM2)
    const int m1   = m0 + 8;

    // ---- A fragments in registers (constant across all 16 tiles) ----
    uint32_t a1r[4][4];            // kW1^T, K=32 -> 4 k-steps
#pragma unroll
    for (int kk = 0; kk < 4; ++kk) {
        int f0 = kk * 8 + tg;
        a1r[kk][0] = to_tf32(kW1[f0 * KDIM + m0]);
        a1r[kk][1] = to_tf32(kW1[f0 * KDIM + m1]);
        a1r[kk][2] = to_tf32(kW1[(f0 + 4) * KDIM + m0]);
        a1r[kk][3] = to_tf32(kW1[(f0 + 4) * KDIM + m1]);
    }
    uint32_t a2r[16][4];           // kW2^T, K=128 -> 16 k-steps
#pragma unroll
    for (int kk = 0; kk < 16; ++kk) {
        int mm = kk * 8 + tg;
        a2r[kk][0] = to_tf32(kW2[mm * KDIM + m0]);
        a2r[kk][1] = to_tf32(kW2[mm * KDIM + m1]);
        a2r[kk][2] = to_tf32(kW2[(mm + 4) * KDIM + m0]);
        a2r[kk][3] = to_tf32(kW2[(mm + 4) * KDIM + m1]);
    }
    const float kb1a = kb1[m0], kb1b = kb1[m1];
    const float kb2a = kb2[m0], kb2b = kb2[m1];

    const int bi0 = blockIdx.x * TILES_PER_CTA;
    const int b   = bi0 >> 6;      // all 16 tiles share the same batch index

    // ---- stage zs[b] into SMEM once per CTA (reused by all 16 tiles) ----
    {
        const float* zsb = g_zs + (size_t)b * (N_PART * KDIM);
        for (int idx = tid; idx < (N_PART * KDIM) / 4; idx += 256) {
            int j = idx >> 5, q = idx & 31;          // 32 float4 per row
            float4 v = *(const float4*)(zsb + j * KDIM + q * 4);
            *(float4*)&zs_s[j * ZPAD + q * 4] = v;
        }
    }

#pragma unroll 1
    for (int t = 0; t < TILES_PER_CTA; ++t) {
        const int bi = bi0 + t;
        const int i  = bi & 63;

        // ---- fill d_s: dists[b,i] (80 x 32) as tf32, row pad DPAD ----
        {
            const float* dptr = dists + (size_t)bi * (N_PART * BASIS);
            for (int idx = tid; idx < N_PART * 8; idx += 256) {
                int j = idx >> 3, q = idx & 7;
                float4 v = *(const float4*)(dptr + j * BASIS + q * 4);
                uint4 u;
                u.x = to_tf32(v.x); u.y = to_tf32(v.y);
                u.z = to_tf32(v.z); u.w = to_tf32(v.w);
                *(uint4*)&d_s[j * DPAD + q * 4] = u;
            }
        }
        __syncthreads();   // d_s ready; also: all warps past prev GEMM2 -> h_s writable

        // ---- GEMM1: 4 k-steps x 10 n-tiles ----
        float acc[10][4];
#pragma unroll
        for (int nt = 0; nt < 10; ++nt) {
            acc[nt][0] = 0.0f; acc[nt][1] = 0.0f;
            acc[nt][2] = 0.0f; acc[nt][3] = 0.0f;
        }
#pragma unroll
        for (int kk = 0; kk < 4; ++kk) {
            const int f = kk * 8 + tg;
#pragma unroll
            for (int nt = 0; nt < 10; ++nt) {
                const int j = nt * 8 + g;
                uint32_t b0v = __float_as_uint(d_s[j * DPAD + f]);
                uint32_t b1v = __float_as_uint(d_s[j * DPAD + f + 4]);
                mma_tf32(acc[nt], a1r[kk], b0v, b1v);
            }
        }

        // ---- epilogue 1: h = ssp(D1 + kb1) -> h_s (tf32 bits) ----
#pragma unroll
        for (int nt = 0; nt < 10; ++nt) {
            const int j0 = nt * 8 + 2 * tg;
            uint2 r0, r1;
            r0.x = to_tf32(ssp_f(acc[nt][0] + kb1a));   // (m0, j0)
            r0.y = to_tf32(ssp_f(acc[nt][1] + kb1a));   // (m0, j0+1)
            r1.x = to_tf32(ssp_f(acc[nt][2] + kb1b));   // (m1, j0)
            r1.y = to_tf32(ssp_f(acc[nt][3] + kb1b));   // (m1, j0+1)
            *(uint2*)&h_s[m0 * HPAD + j0] = r0;
            *(uint2*)&h_s[m1 * HPAD + j0] = r1;
        }
        __syncthreads();   // h_s ready for GEMM2

        // ---- GEMM2: 16 k-steps x 10 n-tiles ----
#pragma unroll
        for (int nt = 0; nt < 10; ++nt) {
            acc[nt][0] = 0.0f; acc[nt][1] = 0.0f;
            acc[nt][2] = 0.0f; acc[nt][3] = 0.0f;
        }
#pragma unroll
        for (int kk = 0; kk < 16; ++kk) {
            const int mm = kk * 8 + tg;
#pragma unroll
            for (int nt = 0; nt < 10; ++nt) {
                const int j = nt * 8 + g;
                uint32_t b0v = __float_as_uint(h_s[mm * HPAD + j]);
                uint32_t b1v = __float_as_uint(h_s[(mm + 4) * HPAD + j]);
                mma_tf32(acc[nt], a2r[kk], b0v, b1v);
            }
        }

        // ---- epilogue 2: mask j==i, weight by zs, reduce j inside warp ----
        float o0 = 0.0f, o1 = 0.0f;
#pragma unroll
        for (int nt = 0; nt < 10; ++nt) {
            const int j0 = nt * 8 + 2 * tg;
            const int j1 = j0 + 1;
            const float w00 = acc[nt][0] + kb2a;   // (k=m0, j0)
            const float w01 = acc[nt][1] + kb2a;   // (k=m0, j1)
            const float w10 = acc[nt][2] + kb2b;   // (k=m1, j0)
            const float w11 = acc[nt][3] + kb2b;   // (k=m1, j1)
            if (j0 != i) {
                o0 = fmaf(w00, zs_s[j0 * ZPAD + m0], o0);
                o1 = fmaf(w10, zs_s[j0 * ZPAD + m1], o1);
            }
            if (j1 != i) {
                o0 = fmaf(w01, zs_s[j1 * ZPAD + m0], o0);
                o1 = fmaf(w11, zs_s[j1 * ZPAD + m1], o1);
            }
        }
        // reduce over tg (lane bits 0,1): j-partials -> full sum per k row
        o0 += __shfl_xor_sync(0xFFFFFFFFu, o0, 1);
        o0 += __shfl_xor_sync(0xFFFFFFFFu, o0, 2);
        o1 += __shfl_xor_sync(0xFFFFFFFFu, o1, 1);
        o1 += __shfl_xor_sync(0xFFFFFFFFu, o1, 2);
        if (tg == 0) {
            g_zsout[(size_t)bi * KDIM + m0] = o0;
            g_zsout[(size_t)bi * KDIM + m1] = o1;
        }
        // no extra sync needed: next-tile d_s fill only races GEMM1 reads,
        // which are fenced by this tile's mid sync; h_s writes are fenced by
        // the next tile's first sync.
    }
}

// ---------------------------------------------------------------------------
// Output MLP: 8 rows per block with weight reuse
// ---------------------------------------------------------------------------
__global__ void __launch_bounds__(128) out_mlp_kernel(const float* __restrict__ eoW1,
                                                      const float* __restrict__ eob1,
                                                      const float* __restrict__ eoW2,
                                                      const float* __restrict__ eob2,
                                                      float* __restrict__ xs) {
    int bi0 = blockIdx.x * 8;
    __shared__ float zr[8][KDIM];
    __shared__ float tr[8][KDIM];
    int k = threadIdx.x;
#pragma unroll
    for (int r = 0; r < 8; ++r) zr[r][k] = g_zsout[(size_t)(bi0 + r) * KDIM + k];
    __syncthreads();
    float acc[8];
    float b1 = eob1[k];
#pragma unroll
    for (int r = 0; r < 8; ++r) acc[r] = b1;
#pragma unroll 4
    for (int d = 0; d < KDIM; ++d) {
        float w = eoW1[d * DDIM + k];
#pragma unroll
        for (int r = 0; r < 8; ++r) acc[r] = fmaf(zr[r][d], w, acc[r]);
    }
#pragma unroll
    for (int r = 0; r < 8; ++r) tr[r][k] = ssp_f(acc[r]);
    __syncthreads();
    float b2 = eob2[k];
#pragma unroll
    for (int r = 0; r < 8; ++r) acc[r] = b2;
#pragma unroll 4
    for (int d = 0; d < DDIM; ++d) {
        float w = eoW2[d * DDIM + k];
#pragma unroll
        for (int r = 0; r < 8; ++r) acc[r] = fmaf(tr[r][d], w, acc[r]);
    }
#pragma unroll
    for (int r = 0; r < 8; ++r) xs[(size_t)(bi0 + r) * DDIM + k] += acc[r];
}

// ---------------------------------------------------------------------------
extern "C" void kernel_launch(void* const* d_in, const int* in_sizes, int n_in,
                              void* d_out, int out_size) {
    const float* dists = (const float*)d_in[0];
    const float* emb_e = (const float*)d_in[1];
    const float* emb_n = (const float*)d_in[2];
    const float* kW1   = (const float*)d_in[3];
    const float* kb1   = (const float*)d_in[4];
    const float* kW2   = (const float*)d_in[5];
    const float* kb2   = (const float*)d_in[6];
    const float* eiW   = (const float*)d_in[7];
    const float* eoW1  = (const float*)d_in[8];
    const float* eob1  = (const float*)d_in[9];
    const float* eoW2  = (const float*)d_in[10];
    const float* eob2  = (const float*)d_in[11];
    float* xs = (float*)d_out;

    const int smem_bytes = (N_PART * DPAD + KDIM * HPAD + N_PART * ZPAD) * 4;
    cudaFuncSetAttribute(cfconv_mma_kernel,
                         cudaFuncAttributeMaxDynamicSharedMemorySize, smem_bytes);

    init_kernel<<<(BSZ * N_ELEC * DDIM + 255) / 256, 256>>>(emb_e, emb_n, xs);

    for (int l = 0; l < LAYERS; ++l) {
        zs_elec_kernel<<<NBI / 8, 128>>>(xs, eiW + (size_t)l * DDIM * KDIM);
        cfconv_mma_kernel<<<CFC_GRID, 256, smem_bytes>>>(dists,
                                    kW1 + (size_t)l * BASIS * KDIM,
                                    kb1 + (size_t)l * KDIM,
                                    kW2 + (size_t)l * KDIM * KDIM,
                                    kb2 + (size_t)l * KDIM);
        out_mlp_kernel<<<NBI / 8, 128>>>(eoW1 + (size_t)l * KDIM * DDIM,
                                     eob1 + (size_t)l * DDIM,
                                     eoW2 + (size_t)l * DDIM * DDIM,
                                     eob2 + (size_t)l * DDIM,
                                     xs);
    }
}

// round 6
// speedup vs baseline: 5.8146x; 1.6255x over previous
#include <cuda_runtime.h>
#include <cuda_fp16.h>
#include <math.h>
#include <stdint.h>

#define N_ELEC 64
#define N_NUC  16
#define N_PART 80
#define BASIS  32
#define KDIM   128
#define DDIM   128
#define BSZ    256
#define LAYERS 3
#define NBI    (BSZ * N_ELEC)

#define TILES_PER_CTA 16
#define CFC_GRID (NBI / TILES_PER_CTA)

// SMEM word-layout (4-byte words)
#define DPADW 20    // d_s row stride in words (40 halves; 32 used) ; 20 mod 32 = 20, frag addrs conflict-free
#define HPADW 68    // h_s row stride in words (136 halves; 128 used); 68 mod 32 = 4 -> conflict-free frags
#define ZPAD  132   // zs_s row stride in floats
#define SMEM_WORDS (N_PART * DPADW + N_PART * HPADW + N_PART * ZPAD)  // 1600 + 5440 + 10560 = 17600 words = 70400 B

// Scratch (no cudaMalloc allowed)
__device__ float g_zs[BSZ * N_PART * KDIM];      // (b, j, k)
__device__ float g_zsout[BSZ * N_ELEC * KDIM];   // cfconv output

__device__ __forceinline__ float ssp_f(float x) {
    float ax = fabsf(x);
    return fmaxf(x, 0.0f) + __logf(1.0f + __expf(-ax)) - 0.69314718055994530942f;
}

__device__ __forceinline__ uint32_t pack_h2(float lo, float hi) {
    __half2 h = __floats2half2_rn(lo, hi);
    return *(uint32_t*)&h;
}

// m16n8k16 fp16 mma, fp32 accumulate (baseline PTX, sm_80+)
__device__ __forceinline__ void mma_f16(float* d, const uint32_t* a,
                                        uint32_t b0, uint32_t b1) {
    asm volatile(
        "mma.sync.aligned.m16n8k16.row.col.f32.f16.f16.f32 "
        "{%0,%1,%2,%3}, {%4,%5,%6,%7}, {%8,%9}, {%0,%1,%2,%3};"
        : "+f"(d[0]), "+f"(d[1]), "+f"(d[2]), "+f"(d[3])
        : "r"(a[0]), "r"(a[1]), "r"(a[2]), "r"(a[3]), "r"(b0), "r"(b1));
}

// ---------------------------------------------------------------------------
__global__ void init_kernel(const float* __restrict__ emb_e,
                            const float* __restrict__ emb_n,
                            float* __restrict__ xs) {
    int idx = blockIdx.x * blockDim.x + threadIdx.x;
    const int total_x = BSZ * N_ELEC * DDIM;
    const int total_n = BSZ * N_NUC * KDIM;
    if (idx < total_x) xs[idx] = emb_e[idx % (N_ELEC * DDIM)];
    if (idx < total_n) {
        int b = idx / (N_NUC * KDIM);
        int r = idx % (N_NUC * KDIM);
        g_zs[b * (N_PART * KDIM) + N_ELEC * KDIM + r] = emb_n[r];
    }
}

// ---------------------------------------------------------------------------
// zs electron rows: 8 rows per block, weight reuse across rows
// ---------------------------------------------------------------------------
__global__ void __launch_bounds__(128) zs_elec_kernel(const float* __restrict__ xs,
                                                      const float* __restrict__ eiW) {
    int bj0 = blockIdx.x * 8;
    int b   = bj0 >> 6;
    int jb  = bj0 & 63;
    __shared__ float xr[8][DDIM];
    int k = threadIdx.x;
#pragma unroll
    for (int r = 0; r < 8; ++r) xr[r][k] = xs[(size_t)(bj0 + r) * DDIM + k];
    __syncthreads();
    float acc[8];
#pragma unroll
    for (int r = 0; r < 8; ++r) acc[r] = 0.0f;
#pragma unroll 4
    for (int d = 0; d < DDIM; ++d) {
        float w = eiW[d * KDIM + k];
#pragma unroll
        for (int r = 0; r < 8; ++r) acc[r] = fmaf(xr[r][d], w, acc[r]);
    }
#pragma unroll
    for (int r = 0; r < 8; ++r)
        g_zs[((size_t)b * N_PART + jb + r) * KDIM + k] = acc[r];
}

// ---------------------------------------------------------------------------
// cfconv via mma.sync fp16 (fp32 accum), persistent CTAs, 2 CTAs/SM
//   GEMM1: D1[m, j] = kW1^T(128x32) @ dists^T(32x80)   -> h = ssp(D1 + kb1)
//   GEMM2: D2[k, j] = kW2^T(128x128) @ h(128x80)
//   out[k] = sum_{j != i} (D2[k,j] + kb2[k]) * zs[b,j,k]
// Warp w owns 16 rows (m/k = w*16..w*16+15); j lives inside the warp.
// B operands stored K-contiguous as halves: one 32-bit LDS per fragment reg.
// ---------------------------------------------------------------------------
extern __shared__ uint32_t cf_smem_w[];

__global__ void __launch_bounds__(256, 2) cfconv_mma_kernel(
    const float* __restrict__ dists,
    const float* __restrict__ kW1, const float* __restrict__ kb1,
    const float* __restrict__ kW2, const float* __restrict__ kb2)
{
    uint32_t* d_sw = cf_smem_w;                         // 80 x DPADW words
    uint32_t* h_sw = cf_smem_w + N_PART * DPADW;        // 80 x HPADW words
    float*    zs_s = (float*)(cf_smem_w + N_PART * (DPADW + HPADW)); // 80 x ZPAD floats
    __half*   h_sh = (__half*)h_sw;                     // index j*2*HPADW + m

    const int tid  = threadIdx.x;
    const int wid  = tid >> 5;
    const int lane = tid & 31;
    const int g    = lane >> 2;    // groupID 0..7
    const int tg   = lane & 3;     // thread-in-group 0..3
    const int m0   = wid * 16 + g; // rows (m for GEMM1, k for GEMM2)
    const int m1   = m0 + 8;

    // ---- A fragments in registers (constant across all 16 tiles) ----
    uint32_t a1r[2][4];            // kW1^T, K=32 -> 2 k16-steps
#pragma unroll
    for (int kk = 0; kk < 2; ++kk) {
        int f = kk * 16 + 2 * tg;
        a1r[kk][0] = pack_h2(kW1[f * KDIM + m0],       kW1[(f + 1) * KDIM + m0]);
        a1r[kk][1] = pack_h2(kW1[f * KDIM + m1],       kW1[(f + 1) * KDIM + m1]);
        a1r[kk][2] = pack_h2(kW1[(f + 8) * KDIM + m0], kW1[(f + 9) * KDIM + m0]);
        a1r[kk][3] = pack_h2(kW1[(f + 8) * KDIM + m1], kW1[(f + 9) * KDIM + m1]);
    }
    uint32_t a2r[8][4];            // kW2^T, K=128 -> 8 k16-steps
#pragma unroll
    for (int kk = 0; kk < 8; ++kk) {
        int mm = kk * 16 + 2 * tg;
        a2r[kk][0] = pack_h2(kW2[mm * KDIM + m0],       kW2[(mm + 1) * KDIM + m0]);
        a2r[kk][1] = pack_h2(kW2[mm * KDIM + m1],       kW2[(mm + 1) * KDIM + m1]);
        a2r[kk][2] = pack_h2(kW2[(mm + 8) * KDIM + m0], kW2[(mm + 9) * KDIM + m0]);
        a2r[kk][3] = pack_h2(kW2[(mm + 8) * KDIM + m1], kW2[(mm + 9) * KDIM + m1]);
    }
    const float kb1a = kb1[m0], kb1b = kb1[m1];
    const float kb2a = kb2[m0], kb2b = kb2[m1];

    const int bi0 = blockIdx.x * TILES_PER_CTA;
    const int b   = bi0 >> 6;      // all 16 tiles share the same batch index

    // ---- stage zs[b] into SMEM once per CTA ----
    {
        const float* zsb = g_zs + (size_t)b * (N_PART * KDIM);
        for (int idx = tid; idx < (N_PART * KDIM) / 4; idx += 256) {
            int j = idx >> 5, q = idx & 31;
            float4 v = *(const float4*)(zsb + j * KDIM + q * 4);
            *(float4*)&zs_s[j * ZPAD + q * 4] = v;
        }
    }

#pragma unroll 1
    for (int t = 0; t < TILES_PER_CTA; ++t) {
        const int bi = bi0 + t;
        const int i  = bi & 63;

        // ---- fill d_s: dists[b,i] (80 x 32) -> half2, row stride DPADW ----
        {
            const float* dptr = dists + (size_t)bi * (N_PART * BASIS);
            for (int idx = tid; idx < N_PART * (BASIS / 2); idx += 256) {
                int j = idx >> 4, q = idx & 15;
                float2 v = *(const float2*)(dptr + j * BASIS + q * 2);
                d_sw[j * DPADW + q] = pack_h2(v.x, v.y);
            }
        }
        __syncthreads();   // d_s ready

        // ---- GEMM1: 2 k16-steps x 10 n-tiles ----
        float acc[10][4];
#pragma unroll
        for (int nt = 0; nt < 10; ++nt) {
            acc[nt][0] = 0.0f; acc[nt][1] = 0.0f;
            acc[nt][2] = 0.0f; acc[nt][3] = 0.0f;
        }
#pragma unroll
        for (int kk = 0; kk < 2; ++kk) {
#pragma unroll
            for (int nt = 0; nt < 10; ++nt) {
                const int j = nt * 8 + g;
                uint32_t b0v = d_sw[j * DPADW + kk * 8 + tg];
                uint32_t b1v = d_sw[j * DPADW + kk * 8 + tg + 4];
                mma_f16(acc[nt], a1r[kk], b0v, b1v);
            }
        }

        // ---- epilogue 1: h = ssp(D1 + kb1) -> h_s[j][m] halves ----
#pragma unroll
        for (int nt = 0; nt < 10; ++nt) {
            const int j0 = nt * 8 + 2 * tg;
            const int j1 = j0 + 1;
            h_sh[j0 * (2 * HPADW) + m0] = __float2half_rn(ssp_f(acc[nt][0] + kb1a));
            h_sh[j1 * (2 * HPADW) + m0] = __float2half_rn(ssp_f(acc[nt][1] + kb1a));
            h_sh[j0 * (2 * HPADW) + m1] = __float2half_rn(ssp_f(acc[nt][2] + kb1b));
            h_sh[j1 * (2 * HPADW) + m1] = __float2half_rn(ssp_f(acc[nt][3] + kb1b));
        }
        __syncthreads();   // h_s ready

        // ---- GEMM2: 8 k16-steps x 10 n-tiles ----
#pragma unroll
        for (int nt = 0; nt < 10; ++nt) {
            acc[nt][0] = 0.0f; acc[nt][1] = 0.0f;
            acc[nt][2] = 0.0f; acc[nt][3] = 0.0f;
        }
#pragma unroll
        for (int kk = 0; kk < 8; ++kk) {
#pragma unroll
            for (int nt = 0; nt < 10; ++nt) {
                const int j = nt * 8 + g;
                uint32_t b0v = h_sw[j * HPADW + kk * 8 + tg];
                uint32_t b1v = h_sw[j * HPADW + kk * 8 + tg + 4];
                mma_f16(acc[nt], a2r[kk], b0v, b1v);
            }
        }

        // ---- epilogue 2: mask j==i, weight by zs, reduce j inside warp ----
        float o0 = 0.0f, o1 = 0.0f;
#pragma unroll
        for (int nt = 0; nt < 10; ++nt) {
            const int j0 = nt * 8 + 2 * tg;
            const int j1 = j0 + 1;
            const float w00 = acc[nt][0] + kb2a;   // (k=m0, j0)
            const float w01 = acc[nt][1] + kb2a;   // (k=m0, j1)
            const float w10 = acc[nt][2] + kb2b;   // (k=m1, j0)
            const float w11 = acc[nt][3] + kb2b;   // (k=m1, j1)
            if (j0 != i) {
                o0 = fmaf(w00, zs_s[j0 * ZPAD + m0], o0);
                o1 = fmaf(w10, zs_s[j0 * ZPAD + m1], o1);
            }
            if (j1 != i) {
                o0 = fmaf(w01, zs_s[j1 * ZPAD + m0], o0);
                o1 = fmaf(w11, zs_s[j1 * ZPAD + m1], o1);
            }
        }
        o0 += __shfl_xor_sync(0xFFFFFFFFu, o0, 1);
        o0 += __shfl_xor_sync(0xFFFFFFFFu, o0, 2);
        o1 += __shfl_xor_sync(0xFFFFFFFFu, o1, 1);
        o1 += __shfl_xor_sync(0xFFFFFFFFu, o1, 2);
        if (tg == 0) {
            g_zsout[(size_t)bi * KDIM + m0] = o0;
            g_zsout[(size_t)bi * KDIM + m1] = o1;
        }
        // 2 syncs/tile suffice: d_s fill (next tile) races only GEMM1 reads,
        // fenced by this tile's mid sync; h_s writes fenced by next first sync.
    }
}

// ---------------------------------------------------------------------------
// Output MLP: 8 rows per block with weight reuse
// ---------------------------------------------------------------------------
__global__ void __launch_bounds__(128) out_mlp_kernel(const float* __restrict__ eoW1,
                                                      const float* __restrict__ eob1,
                                                      const float* __restrict__ eoW2,
                                                      const float* __restrict__ eob2,
                                                      float* __restrict__ xs) {
    int bi0 = blockIdx.x * 8;
    __shared__ float zr[8][KDIM];
    __shared__ float tr[8][KDIM];
    int k = threadIdx.x;
#pragma unroll
    for (int r = 0; r < 8; ++r) zr[r][k] = g_zsout[(size_t)(bi0 + r) * KDIM + k];
    __syncthreads();
    float acc[8];
    float b1 = eob1[k];
#pragma unroll
    for (int r = 0; r < 8; ++r) acc[r] = b1;
#pragma unroll 4
    for (int d = 0; d < KDIM; ++d) {
        float w = eoW1[d * DDIM + k];
#pragma unroll
        for (int r = 0; r < 8; ++r) acc[r] = fmaf(zr[r][d], w, acc[r]);
    }
#pragma unroll
    for (int r = 0; r < 8; ++r) tr[r][k] = ssp_f(acc[r]);
    __syncthreads();
    float b2 = eob2[k];
#pragma unroll
    for (int r = 0; r < 8; ++r) acc[r] = b2;
#pragma unroll 4
    for (int d = 0; d < DDIM; ++d) {
        float w = eoW2[d * DDIM + k];
#pragma unroll
        for (int r = 0; r < 8; ++r) acc[r] = fmaf(tr[r][d], w, acc[r]);
    }
#pragma unroll
    for (int r = 0; r < 8; ++r) xs[(size_t)(bi0 + r) * DDIM + k] += acc[r];
}

// ---------------------------------------------------------------------------
extern "C" void kernel_launch(void* const* d_in, const int* in_sizes, int n_in,
                              void* d_out, int out_size) {
    const float* dists = (const float*)d_in[0];
    const float* emb_e = (const float*)d_in[1];
    const float* emb_n = (const float*)d_in[2];
    const float* kW1   = (const float*)d_in[3];
    const float* kb1   = (const float*)d_in[4];
    const float* kW2   = (const float*)d_in[5];
    const float* kb2   = (const float*)d_in[6];
    const float* eiW   = (const float*)d_in[7];
    const float* eoW1  = (const float*)d_in[8];
    const float* eob1  = (const float*)d_in[9];
    const float* eoW2  = (const float*)d_in[10];
    const float* eob2  = (const float*)d_in[11];
    float* xs = (float*)d_out;

    const int smem_bytes = SMEM_WORDS * 4;
    cudaFuncSetAttribute(cfconv_mma_kernel,
                         cudaFuncAttributeMaxDynamicSharedMemorySize, smem_bytes);

    init_kernel<<<(BSZ * N_ELEC * DDIM + 255) / 256, 256>>>(emb_e, emb_n, xs);

    for (int l = 0; l < LAYERS; ++l) {
        zs_elec_kernel<<<NBI / 8, 128>>>(xs, eiW + (size_t)l * DDIM * KDIM);
        cfconv_mma_kernel<<<CFC_GRID, 256, smem_bytes>>>(dists,
                                    kW1 + (size_t)l * BASIS * KDIM,
                                    kb1 + (size_t)l * KDIM,
                                    kW2 + (size_t)l * KDIM * KDIM,
                                    kb2 + (size_t)l * KDIM);
        out_mlp_kernel<<<NBI / 8, 128>>>(eoW1 + (size_t)l * KDIM * DDIM,
                                     eob1 + (size_t)l * DDIM,
                                     eoW2 + (size_t)l * DDIM * DDIM,
                                     eob2 + (size_t)l * DDIM,
                                     xs);
    }
}

// round 7
// speedup vs baseline: 6.7994x; 1.1694x over previous
#include <cuda_runtime.h>
#include <cuda_fp16.h>
#include <math.h>
#include <stdint.h>

#define N_ELEC 64
#define N_NUC  16
#define N_PART 80
#define BASIS  32
#define KDIM   128
#define DDIM   128
#define BSZ    256
#define LAYERS 3
#define NBI    (BSZ * N_ELEC)

#define TILES_PER_CTA 8
#define CFC_GRID (NBI / TILES_PER_CTA)

// cfconv SMEM word-layout (4-byte words)
#define DPADW 20
#define HPADW 68
#define ZPAD  132
#define SMEM_WORDS (N_PART * DPADW + N_PART * HPADW + N_PART * ZPAD)

// side-kernel SMEM row stride (words): 64 data words + 4 pad -> banks 4*r
#define ASTR 68

// Scratch (no cudaMalloc allowed)
__device__ float g_zs[BSZ * N_PART * KDIM];      // (b, j, k)
__device__ float g_zsout[BSZ * N_ELEC * KDIM];   // cfconv output

__device__ __forceinline__ float ssp_f(float x) {
    float ax = fabsf(x);
    return fmaxf(x, 0.0f) + __logf(1.0f + __expf(-ax)) - 0.69314718055994530942f;
}

__device__ __forceinline__ uint32_t pack_h2(float lo, float hi) {
    __half2 h = __floats2half2_rn(lo, hi);
    return *(uint32_t*)&h;
}

// m16n8k16 fp16 mma, fp32 accumulate (baseline PTX, sm_80+)
__device__ __forceinline__ void mma_f16(float* d, const uint32_t* a,
                                        uint32_t b0, uint32_t b1) {
    asm volatile(
        "mma.sync.aligned.m16n8k16.row.col.f32.f16.f16.f32 "
        "{%0,%1,%2,%3}, {%4,%5,%6,%7}, {%8,%9}, {%0,%1,%2,%3};"
        : "+f"(d[0]), "+f"(d[1]), "+f"(d[2]), "+f"(d[3])
        : "r"(a[0]), "r"(a[1]), "r"(a[2]), "r"(a[3]), "r"(b0), "r"(b1));
}

// ---------------------------------------------------------------------------
__global__ void init_kernel(const float* __restrict__ emb_e,
                            const float* __restrict__ emb_n,
                            float* __restrict__ xs) {
    int idx = blockIdx.x * blockDim.x + threadIdx.x;
    const int total_x = BSZ * N_ELEC * DDIM;
    const int total_n = BSZ * N_NUC * KDIM;
    if (idx < total_x) xs[idx] = emb_e[idx % (N_ELEC * DDIM)];
    if (idx < total_n) {
        int b = idx / (N_NUC * KDIM);
        int r = idx % (N_NUC * KDIM);
        g_zs[b * (N_PART * KDIM) + N_ELEC * KDIM + r] = emb_n[r];
    }
}

// ---------------------------------------------------------------------------
// zs electron rows via mma: zs[r, k] = sum_d xs[r, d] * eiW[d, k]
// 128 rows per CTA (grid = 128), 8 warps x 16 rows.
// ---------------------------------------------------------------------------
extern __shared__ uint32_t dyn_smem_w[];

__global__ void __launch_bounds__(256) zs_elec_mma_kernel(
    const float* __restrict__ xs, const float* __restrict__ eiW)
{
    uint32_t* w_w = dyn_smem_w;                  // eiW^T: [k][d-halves], 128 x ASTR
    uint32_t* a_w = dyn_smem_w + 128 * ASTR;     // xs rows fp16:  [r][d-halves]

    const int tid  = threadIdx.x;
    const int wid  = tid >> 5;
    const int lane = tid & 31;
    const int g    = lane >> 2;
    const int tg   = lane & 3;
    const int rblk = blockIdx.x * 128;
    const int r0   = wid * 16 + g;

    // stage eiW^T  (reads coalesced over k)
    for (int idx = tid; idx < 128 * 64; idx += 256) {
        int dp = idx >> 7, k = idx & 127;
        w_w[k * ASTR + dp] = pack_h2(eiW[(2 * dp) * KDIM + k],
                                     eiW[(2 * dp + 1) * KDIM + k]);
    }
    // stage xs rows as fp16 (float2 coalesced)
    for (int idx = tid; idx < 128 * 64; idx += 256) {
        int r = idx >> 6, dw = idx & 63;
        float2 v = *(const float2*)&xs[(size_t)(rblk + r) * DDIM + dw * 2];
        a_w[r * ASTR + dw] = pack_h2(v.x, v.y);
    }
    __syncthreads();

    float acc[16][4];
#pragma unroll
    for (int nt = 0; nt < 16; ++nt) {
        acc[nt][0] = 0.f; acc[nt][1] = 0.f; acc[nt][2] = 0.f; acc[nt][3] = 0.f;
    }
#pragma unroll
    for (int kk = 0; kk < 8; ++kk) {
        uint32_t a[4];
        int ab = r0 * ASTR + kk * 8 + tg;
        a[0] = a_w[ab];
        a[1] = a_w[ab + 8 * ASTR];
        a[2] = a_w[ab + 4];
        a[3] = a_w[ab + 8 * ASTR + 4];
#pragma unroll
        for (int nt = 0; nt < 16; ++nt) {
            int nb = (nt * 8 + g) * ASTR + kk * 8 + tg;
            mma_f16(acc[nt], a, w_w[nb], w_w[nb + 4]);
        }
    }

    // store fp32 to g_zs (row -> (b, j))
    const int row0 = rblk + r0;
    const int b0 = row0 >> 6, j0 = row0 & 63;
    const int row1 = row0 + 8;
    const int b1 = row1 >> 6, j1 = row1 & 63;
    float* z0 = g_zs + ((size_t)b0 * N_PART + j0) * KDIM;
    float* z1 = g_zs + ((size_t)b1 * N_PART + j1) * KDIM;
#pragma unroll
    for (int nt = 0; nt < 16; ++nt) {
        int k0 = nt * 8 + 2 * tg;
        *(float2*)&z0[k0] = make_float2(acc[nt][0], acc[nt][1]);
        *(float2*)&z1[k0] = make_float2(acc[nt][2], acc[nt][3]);
    }
}

// ---------------------------------------------------------------------------
// Output MLP via mma: xs += ssp(zsout @ eoW1 + eob1) @ eoW2 + eob2
// 128 rows per CTA (grid = 128). T (intermediate) aliases the eoW1 buffer.
// ---------------------------------------------------------------------------
__global__ void __launch_bounds__(256) out_mlp_mma_kernel(
    const float* __restrict__ eoW1, const float* __restrict__ eob1,
    const float* __restrict__ eoW2, const float* __restrict__ eob2,
    float* __restrict__ xs)
{
    uint32_t* w1_w = dyn_smem_w;                    // eoW1^T -> later T rows
    uint32_t* w2_w = dyn_smem_w + 128 * ASTR;       // eoW2^T
    uint32_t* a_w  = dyn_smem_w + 2 * 128 * ASTR;   // zsout rows fp16
    float*    bias = (float*)(dyn_smem_w + 3 * 128 * ASTR); // 256 floats

    const int tid  = threadIdx.x;
    const int wid  = tid >> 5;
    const int lane = tid & 31;
    const int g    = lane >> 2;
    const int tg   = lane & 3;
    const int rblk = blockIdx.x * 128;
    const int r0   = wid * 16 + g;

    // stage weights transposed (reads coalesced over d)
    for (int idx = tid; idx < 128 * 64; idx += 256) {
        int kp = idx >> 7, d = idx & 127;
        w1_w[d * ASTR + kp] = pack_h2(eoW1[(2 * kp) * DDIM + d],
                                      eoW1[(2 * kp + 1) * DDIM + d]);
        w2_w[d * ASTR + kp] = pack_h2(eoW2[(2 * kp) * DDIM + d],
                                      eoW2[(2 * kp + 1) * DDIM + d]);
    }
    // stage zsout rows fp16
    for (int idx = tid; idx < 128 * 64; idx += 256) {
        int r = idx >> 6, kw = idx & 63;
        float2 v = *(const float2*)&g_zsout[(size_t)(rblk + r) * KDIM + kw * 2];
        a_w[r * ASTR + kw] = pack_h2(v.x, v.y);
    }
    if (tid < 128) { bias[tid] = eob1[tid]; bias[128 + tid] = eob2[tid]; }
    __syncthreads();

    float acc[16][4];
#pragma unroll
    for (int nt = 0; nt < 16; ++nt) {
        acc[nt][0] = 0.f; acc[nt][1] = 0.f; acc[nt][2] = 0.f; acc[nt][3] = 0.f;
    }
    // GEMM1: zsout @ eoW1
#pragma unroll
    for (int kk = 0; kk < 8; ++kk) {
        uint32_t a[4];
        int ab = r0 * ASTR + kk * 8 + tg;
        a[0] = a_w[ab];
        a[1] = a_w[ab + 8 * ASTR];
        a[2] = a_w[ab + 4];
        a[3] = a_w[ab + 8 * ASTR + 4];
#pragma unroll
        for (int nt = 0; nt < 16; ++nt) {
            int nb = (nt * 8 + g) * ASTR + kk * 8 + tg;
            mma_f16(acc[nt], a, w1_w[nb], w1_w[nb + 4]);
        }
    }
    __syncthreads();   // all warps done reading w1 -> reuse as T

    // epilogue 1: T = ssp(C1 + eob1), fp16 into w1_w
#pragma unroll
    for (int nt = 0; nt < 16; ++nt) {
        int d0 = nt * 8 + 2 * tg;
        float ba = bias[d0], bb = bias[d0 + 1];
        w1_w[r0 * ASTR + nt * 4 + tg] =
            pack_h2(ssp_f(acc[nt][0] + ba), ssp_f(acc[nt][1] + bb));
        w1_w[(r0 + 8) * ASTR + nt * 4 + tg] =
            pack_h2(ssp_f(acc[nt][2] + ba), ssp_f(acc[nt][3] + bb));
        acc[nt][0] = 0.f; acc[nt][1] = 0.f; acc[nt][2] = 0.f; acc[nt][3] = 0.f;
    }
    __syncthreads();

    // GEMM2: T @ eoW2
#pragma unroll
    for (int kk = 0; kk < 8; ++kk) {
        uint32_t a[4];
        int ab = r0 * ASTR + kk * 8 + tg;
        a[0] = w1_w[ab];
        a[1] = w1_w[ab + 8 * ASTR];
        a[2] = w1_w[ab + 4];
        a[3] = w1_w[ab + 8 * ASTR + 4];
#pragma unroll
        for (int nt = 0; nt < 16; ++nt) {
            int nb = (nt * 8 + g) * ASTR + kk * 8 + tg;
            mma_f16(acc[nt], a, w2_w[nb], w2_w[nb + 4]);
        }
    }

    // epilogue 2: xs += C2 + eob2
    float* x0 = xs + (size_t)(rblk + r0) * DDIM;
    float* x1 = xs + (size_t)(rblk + r0 + 8) * DDIM;
#pragma unroll
    for (int nt = 0; nt < 16; ++nt) {
        int d0 = nt * 8 + 2 * tg;
        float ba = bias[128 + d0], bb = bias[128 + d0 + 1];
        float2 v0 = *(float2*)&x0[d0];
        float2 v1 = *(float2*)&x1[d0];
        v0.x += acc[nt][0] + ba;  v0.y += acc[nt][1] + bb;
        v1.x += acc[nt][2] + ba;  v1.y += acc[nt][3] + bb;
        *(float2*)&x0[d0] = v0;
        *(float2*)&x1[d0] = v1;
    }
}

// ---------------------------------------------------------------------------
// cfconv via mma.sync fp16 (fp32 accum), persistent CTAs, 2 CTAs/SM
// ---------------------------------------------------------------------------
__global__ void __launch_bounds__(256, 2) cfconv_mma_kernel(
    const float* __restrict__ dists,
    const float* __restrict__ kW1, const float* __restrict__ kb1,
    const float* __restrict__ kW2, const float* __restrict__ kb2)
{
    uint32_t* d_sw = dyn_smem_w;                        // 80 x DPADW words
    uint32_t* h_sw = dyn_smem_w + N_PART * DPADW;       // 80 x HPADW words
    float*    zs_s = (float*)(dyn_smem_w + N_PART * (DPADW + HPADW));
    __half*   h_sh = (__half*)h_sw;

    const int tid  = threadIdx.x;
    const int wid  = tid >> 5;
    const int lane = tid & 31;
    const int g    = lane >> 2;
    const int tg   = lane & 3;
    const int m0   = wid * 16 + g;
    const int m1   = m0 + 8;

    uint32_t a1r[2][4];
#pragma unroll
    for (int kk = 0; kk < 2; ++kk) {
        int f = kk * 16 + 2 * tg;
        a1r[kk][0] = pack_h2(kW1[f * KDIM + m0],       kW1[(f + 1) * KDIM + m0]);
        a1r[kk][1] = pack_h2(kW1[f * KDIM + m1],       kW1[(f + 1) * KDIM + m1]);
        a1r[kk][2] = pack_h2(kW1[(f + 8) * KDIM + m0], kW1[(f + 9) * KDIM + m0]);
        a1r[kk][3] = pack_h2(kW1[(f + 8) * KDIM + m1], kW1[(f + 9) * KDIM + m1]);
    }
    uint32_t a2r[8][4];
#pragma unroll
    for (int kk = 0; kk < 8; ++kk) {
        int mm = kk * 16 + 2 * tg;
        a2r[kk][0] = pack_h2(kW2[mm * KDIM + m0],       kW2[(mm + 1) * KDIM + m0]);
        a2r[kk][1] = pack_h2(kW2[mm * KDIM + m1],       kW2[(mm + 1) * KDIM + m1]);
        a2r[kk][2] = pack_h2(kW2[(mm + 8) * KDIM + m0], kW2[(mm + 9) * KDIM + m0]);
        a2r[kk][3] = pack_h2(kW2[(mm + 8) * KDIM + m1], kW2[(mm + 9) * KDIM + m1]);
    }
    const float kb1a = kb1[m0], kb1b = kb1[m1];
    const float kb2a = kb2[m0], kb2b = kb2[m1];

    const int bi0 = blockIdx.x * TILES_PER_CTA;
    const int b   = bi0 >> 6;      // 8 | 64 -> constant per CTA

    {
        const float* zsb = g_zs + (size_t)b * (N_PART * KDIM);
        for (int idx = tid; idx < (N_PART * KDIM) / 4; idx += 256) {
            int j = idx >> 5, q = idx & 31;
            float4 v = *(const float4*)(zsb + j * KDIM + q * 4);
            *(float4*)&zs_s[j * ZPAD + q * 4] = v;
        }
    }

#pragma unroll 1
    for (int t = 0; t < TILES_PER_CTA; ++t) {
        const int bi = bi0 + t;
        const int i  = bi & 63;

        {
            const float* dptr = dists + (size_t)bi * (N_PART * BASIS);
            for (int idx = tid; idx < N_PART * (BASIS / 2); idx += 256) {
                int j = idx >> 4, q = idx & 15;
                float2 v = *(const float2*)(dptr + j * BASIS + q * 2);
                d_sw[j * DPADW + q] = pack_h2(v.x, v.y);
            }
        }
        __syncthreads();

        float acc[10][4];
#pragma unroll
        for (int nt = 0; nt < 10; ++nt) {
            acc[nt][0] = 0.0f; acc[nt][1] = 0.0f;
            acc[nt][2] = 0.0f; acc[nt][3] = 0.0f;
        }
#pragma unroll
        for (int kk = 0; kk < 2; ++kk) {
#pragma unroll
            for (int nt = 0; nt < 10; ++nt) {
                const int j = nt * 8 + g;
                uint32_t b0v = d_sw[j * DPADW + kk * 8 + tg];
                uint32_t b1v = d_sw[j * DPADW + kk * 8 + tg + 4];
                mma_f16(acc[nt], a1r[kk], b0v, b1v);
            }
        }

#pragma unroll
        for (int nt = 0; nt < 10; ++nt) {
            const int j0 = nt * 8 + 2 * tg;
            const int j1 = j0 + 1;
            h_sh[j0 * (2 * HPADW) + m0] = __float2half_rn(ssp_f(acc[nt][0] + kb1a));
            h_sh[j1 * (2 * HPADW) + m0] = __float2half_rn(ssp_f(acc[nt][1] + kb1a));
            h_sh[j0 * (2 * HPADW) + m1] = __float2half_rn(ssp_f(acc[nt][2] + kb1b));
            h_sh[j1 * (2 * HPADW) + m1] = __float2half_rn(ssp_f(acc[nt][3] + kb1b));
        }
        __syncthreads();

#pragma unroll
        for (int nt = 0; nt < 10; ++nt) {
            acc[nt][0] = 0.0f; acc[nt][1] = 0.0f;
            acc[nt][2] = 0.0f; acc[nt][3] = 0.0f;
        }
#pragma unroll
        for (int kk = 0; kk < 8; ++kk) {
#pragma unroll
            for (int nt = 0; nt < 10; ++nt) {
                const int j = nt * 8 + g;
                uint32_t b0v = h_sw[j * HPADW + kk * 8 + tg];
                uint32_t b1v = h_sw[j * HPADW + kk * 8 + tg + 4];
                mma_f16(acc[nt], a2r[kk], b0v, b1v);
            }
        }

        float o0 = 0.0f, o1 = 0.0f;
#pragma unroll
        for (int nt = 0; nt < 10; ++nt) {
            const int j0 = nt * 8 + 2 * tg;
            const int j1 = j0 + 1;
            const float w00 = acc[nt][0] + kb2a;
            const float w01 = acc[nt][1] + kb2a;
            const float w10 = acc[nt][2] + kb2b;
            const float w11 = acc[nt][3] + kb2b;
            if (j0 != i) {
                o0 = fmaf(w00, zs_s[j0 * ZPAD + m0], o0);
                o1 = fmaf(w10, zs_s[j0 * ZPAD + m1], o1);
            }
            if (j1 != i) {
                o0 = fmaf(w01, zs_s[j1 * ZPAD + m0], o0);
                o1 = fmaf(w11, zs_s[j1 * ZPAD + m1], o1);
            }
        }
        o0 += __shfl_xor_sync(0xFFFFFFFFu, o0, 1);
        o0 += __shfl_xor_sync(0xFFFFFFFFu, o0, 2);
        o1 += __shfl_xor_sync(0xFFFFFFFFu, o1, 1);
        o1 += __shfl_xor_sync(0xFFFFFFFFu, o1, 2);
        if (tg == 0) {
            g_zsout[(size_t)bi * KDIM + m0] = o0;
            g_zsout[(size_t)bi * KDIM + m1] = o1;
        }
    }
}

// ---------------------------------------------------------------------------
extern "C" void kernel_launch(void* const* d_in, const int* in_sizes, int n_in,
                              void* d_out, int out_size) {
    const float* dists = (const float*)d_in[0];
    const float* emb_e = (const float*)d_in[1];
    const float* emb_n = (const float*)d_in[2];
    const float* kW1   = (const float*)d_in[3];
    const float* kb1   = (const float*)d_in[4];
    const float* kW2   = (const float*)d_in[5];
    const float* kb2   = (const float*)d_in[6];
    const float* eiW   = (const float*)d_in[7];
    const float* eoW1  = (const float*)d_in[8];
    const float* eob1  = (const float*)d_in[9];
    const float* eoW2  = (const float*)d_in[10];
    const float* eob2  = (const float*)d_in[11];
    float* xs = (float*)d_out;

    const int cf_smem  = SMEM_WORDS * 4;
    const int zs_smem  = 2 * 128 * ASTR * 4;
    const int om_smem  = (3 * 128 * ASTR + 256) * 4;
    cudaFuncSetAttribute(cfconv_mma_kernel,
                         cudaFuncAttributeMaxDynamicSharedMemorySize, cf_smem);
    cudaFuncSetAttribute(zs_elec_mma_kernel,
                         cudaFuncAttributeMaxDynamicSharedMemorySize, zs_smem);
    cudaFuncSetAttribute(out_mlp_mma_kernel,
                         cudaFuncAttributeMaxDynamicSharedMemorySize, om_smem);

    init_kernel<<<(BSZ * N_ELEC * DDIM + 255) / 256, 256>>>(emb_e, emb_n, xs);

    for (int l = 0; l < LAYERS; ++l) {
        zs_elec_mma_kernel<<<NBI / 128, 256, zs_smem>>>(xs, eiW + (size_t)l * DDIM * KDIM);
        cfconv_mma_kernel<<<CFC_GRID, 256, cf_smem>>>(dists,
                                    kW1 + (size_t)l * BASIS * KDIM,
                                    kb1 + (size_t)l * KDIM,
                                    kW2 + (size_t)l * KDIM * KDIM,
                                    kb2 + (size_t)l * KDIM);
        out_mlp_mma_kernel<<<NBI / 128, 256, om_smem>>>(eoW1 + (size_t)l * KDIM * DDIM,
                                     eob1 + (size_t)l * DDIM,
                                     eoW2 + (size_t)l * DDIM * DDIM,
                                     eob2 + (size_t)l * DDIM,
                                     xs);
    }
}